// round 1
// baseline (speedup 1.0000x reference)
#include <cuda_runtime.h>
#include <cuda_bf16.h>

// GaussianKernelLoss: B=32, N=16, H=W=256, SIGMA=0.1, RADIUS=0.2
// Inputs (metadata order):
//   d_in[0] = pred_landmarks   [32,16,2] float32 (1024 elems)
//   d_in[1] = target_landmarks [32,16,2] float32 (1024 elems)
//   d_in[2] = visibility       [32,16]   float32 (512 elems)
//   d_in[3] = coord_grid       [2,256,256] float32 (131072 elems)
// Output: scalar float32.

#define BN     512            // B*N landmarks
#define HW     65536          // 256*256
#define W      256
#define RADIUS 0.2f
#define R2     (0.2f * 0.2f)
#define COEF   (-50.0f)       // -1/(2*sigma^2), sigma=0.1
#define TBLSZ  112            // max bounding-box extent (2*0.2*255 + margins)

__device__ float g_partial[BN];  // per-landmark num/den results (scratch, rewritten each launch)

__global__ __launch_bounds__(512, 4)
void gkl_main_kernel(const float* __restrict__ pred,
                     const float* __restrict__ tgt,
                     const float* __restrict__ vis,
                     const float* __restrict__ grid)
{
    const int lm  = blockIdx.x;   // landmark index 0..511
    const int tid = threadIdx.x;  // 0..511

    __shared__ float colEx[TBLSZ], colT2[TBLSZ], colP2[TBLSZ];
    __shared__ float rowEy[TBLSZ], rowT2[TBLSZ], rowP2[TBLSZ];
    __shared__ float redN[16], redD[16];

    // Visibility gate: invisible landmarks contribute exactly 0.
    const float v = vis[lm];
    if (v < 0.5f) {
        if (tid == 0) g_partial[lm] = 0.0f;
        return;
    }

    const float tx = tgt[2 * lm + 0];
    const float ty = tgt[2 * lm + 1];
    const float px = pred[2 * lm + 0];
    const float py = pred[2 * lm + 1];

    // Bounding box of the radius-0.2 disk around the target, with 1px safety
    // margin (the exact d<=R mask is applied per-pixel, so the margin is free).
    const int x0 = max(0,   (int)floorf((tx - RADIUS) * 255.0f) - 1);
    const int x1 = min(255, (int)ceilf ((tx + RADIUS) * 255.0f) + 1);
    const int y0 = max(0,   (int)floorf((ty - RADIUS) * 255.0f) - 1);
    const int y1 = min(255, (int)ceilf ((ty + RADIUS) * 255.0f) + 1);
    const int bw = x1 - x0 + 1;
    const int bh = y1 - y0 + 1;

    // Per-column tables: x-coords come from coord_grid channel 0, row 0.
    for (int k = tid; k < bw; k += 512) {
        const float xv = grid[x0 + k];
        const float dt = xv - tx;
        const float dp = xv - px;
        colT2[k] = dt * dt;
        colP2[k] = dp * dp;
        colEx[k] = __expf(COEF * dt * dt);
    }
    // Per-row tables: y-coords come from coord_grid channel 1, column 0.
    for (int k = tid; k < bh; k += 512) {
        const float yv = grid[HW + (y0 + k) * W];
        const float dt = yv - ty;
        const float dp = yv - py;
        rowT2[k] = dt * dt;
        rowP2[k] = dp * dp;
        rowEy[k] = __expf(COEF * dt * dt);
    }
    __syncthreads();

    // Pixel loop: 32 lanes sweep columns, 16 warp-rows sweep rows.
    const int cx = tid & 31;
    const int cy = tid >> 5;

    float num = 0.0f, den = 0.0f;
    for (int i = cy; i < bh; i += 16) {
        const float ey  = rowEy[i];
        const float t2y = rowT2[i];
        const float p2y = rowP2[i];
        for (int j = cx; j < bw; j += 32) {
            const float d2t = colT2[j] + t2y;
            if (d2t <= R2) {
                const float w   = colEx[j] * ey;
                const float d2p = colP2[j] + p2y;
                float dpr;
                asm("sqrt.approx.f32 %0, %1;" : "=f"(dpr) : "f"(d2p));
                num += w * dpr;
                den += w;
            }
        }
    }

    // Warp reduce, then block reduce.
    #pragma unroll
    for (int o = 16; o; o >>= 1) {
        num += __shfl_xor_sync(0xffffffffu, num, o);
        den += __shfl_xor_sync(0xffffffffu, den, o);
    }
    if (cx == 0) { redN[cy] = num; redD[cy] = den; }
    __syncthreads();
    if (tid == 0) {
        float n = 0.0f, d = 0.0f;
        #pragma unroll
        for (int k = 0; k < 16; k++) { n += redN[k]; d += redD[k]; }
        g_partial[lm] = n / (d + 1e-8f);
    }
}

__global__ void gkl_finalize_kernel(float* __restrict__ out)
{
    const int tid = threadIdx.x;  // 512 threads
    float s = g_partial[tid];
    #pragma unroll
    for (int o = 16; o; o >>= 1) s += __shfl_xor_sync(0xffffffffu, s, o);

    __shared__ float sm[16];
    if ((tid & 31) == 0) sm[tid >> 5] = s;
    __syncthreads();
    if (tid < 16) {
        s = sm[tid];
        #pragma unroll
        for (int o = 8; o; o >>= 1) s += __shfl_xor_sync(0xffffu, s, o);
        if (tid == 0) *out = s / (512.0f + 1e-8f);
    }
}

extern "C" void kernel_launch(void* const* d_in, const int* in_sizes, int n_in,
                              void* d_out, int out_size)
{
    const float* pred = (const float*)d_in[0];
    const float* tgt  = (const float*)d_in[1];
    const float* vis  = (const float*)d_in[2];
    const float* grid = (const float*)d_in[3];
    float* out = (float*)d_out;

    gkl_main_kernel<<<BN, 512>>>(pred, tgt, vis, grid);
    gkl_finalize_kernel<<<1, 512>>>(out);
}

// round 2
// speedup vs baseline: 1.6218x; 1.6218x over previous
#include <cuda_runtime.h>
#include <cuda_bf16.h>

// GaussianKernelLoss: B=32, N=16, H=W=256, SIGMA=0.1, RADIUS=0.2
// Inputs (metadata order):
//   d_in[0] = pred_landmarks   [32,16,2] float32
//   d_in[1] = target_landmarks [32,16,2] float32
//   d_in[2] = visibility       [32,16]   float32
//   d_in[3] = coord_grid       [2,256,256] float32
// Output: scalar float32.

#define BN     512
#define HW     65536
#define W      256
#define RADIUS 0.2f
#define R2     (0.2f * 0.2f)
#define COEF   (-50.0f)       // -1/(2*sigma^2)
#define TBLSZ  112            // max bbox rows
#define NCOL   4              // 4*32 = 128 >= max bbox width (~106)

__device__ float g_partial[BN];
__device__ int   g_count;     // zero-init; last block resets to 0 each launch

__global__ __launch_bounds__(512, 3)
void gkl_fused_kernel(const float* __restrict__ pred,
                      const float* __restrict__ tgt,
                      const float* __restrict__ vis,
                      const float* __restrict__ grid,
                      float* __restrict__ out)
{
    const int lm  = blockIdx.x;
    const int tid = threadIdx.x;
    const int cx  = tid & 31;
    const int cy  = tid >> 5;

    __shared__ float rowEy[TBLSZ], rowT2[TBLSZ], rowP2[TBLSZ];
    __shared__ float redN[16], redD[16];
    __shared__ int   sIsLast;

    float num = 0.0f, den = 0.0f;
    const float v = vis[lm];

    if (v >= 0.5f) {
        const float tx = tgt[2 * lm + 0];
        const float ty = tgt[2 * lm + 1];
        const float px = pred[2 * lm + 0];
        const float py = pred[2 * lm + 1];

        // Bounding box of the radius disk (exact mask applied per-pixel).
        const int x0 = max(0,   (int)floorf((tx - RADIUS) * 255.0f) - 1);
        const int x1 = min(255, (int)ceilf ((tx + RADIUS) * 255.0f) + 1);
        const int y0 = max(0,   (int)floorf((ty - RADIUS) * 255.0f) - 1);
        const int y1 = min(255, (int)ceilf ((ty + RADIUS) * 255.0f) + 1);
        const int bw = x1 - x0 + 1;
        const int bh = y1 - y0 + 1;

        // Row tables (shared, broadcast reads in the pixel loop).
        for (int k = tid; k < bh; k += 512) {
            const float yv = grid[HW + (y0 + k) * W];
            const float dt = yv - ty;
            const float dp = yv - py;
            rowT2[k] = dt * dt;
            rowP2[k] = dp * dp;
            rowEy[k] = __expf(COEF * dt * dt);
        }

        // Column tables (per-lane registers): lane cx owns columns cx+32k.
        // Out-of-range columns poisoned so they contribute exactly 0.
        float cT2[NCOL], cP2[NCOL], cEx[NCOL];
        #pragma unroll
        for (int k = 0; k < NCOL; k++) {
            const int j  = cx + 32 * k;
            const bool ok = (j < bw);
            const float xv = grid[min(x0 + j, 255)];  // row 0 of channel 0
            const float dt = xv - tx;
            const float dp = xv - px;
            cT2[k] = ok ? dt * dt : 1e9f;
            cP2[k] = dp * dp;
            cEx[k] = ok ? __expf(COEF * dt * dt) : 0.0f;
        }
        __syncthreads();

        for (int i = cy; i < bh; i += 16) {
            const float ey  = rowEy[i];
            const float t2y = rowT2[i];
            const float p2y = rowP2[i];
            #pragma unroll
            for (int k = 0; k < NCOL; k++) {
                const float d2t = cT2[k] + t2y;
                const float w   = cEx[k] * ey;
                const float d2p = cP2[k] + p2y;
                float d;
                asm("sqrt.approx.f32 %0, %1;" : "=f"(d) : "f"(d2p));
                const bool in = (d2t <= R2);
                num += in ? w * d : 0.0f;
                den += in ? w     : 0.0f;
            }
        }
    } else {
        __syncthreads();   // keep barrier count uniform across the block
    }

    // Block reduction of (num, den).
    #pragma unroll
    for (int o = 16; o; o >>= 1) {
        num += __shfl_xor_sync(0xffffffffu, num, o);
        den += __shfl_xor_sync(0xffffffffu, den, o);
    }
    if (cx == 0) { redN[cy] = num; redD[cy] = den; }
    __syncthreads();

    if (tid == 0) {
        float n = 0.0f, d = 0.0f;
        #pragma unroll
        for (int k = 0; k < 16; k++) { n += redN[k]; d += redD[k]; }
        g_partial[lm] = n / (d + 1e-8f);   // 0/1e-8 = 0 for invisible
        __threadfence();
        const int c = atomicAdd(&g_count, 1);
        sIsLast = (c == BN - 1);
    }
    __syncthreads();

    // Last block folds all 512 partials into the scalar output.
    if (sIsLast) {
        float s = __ldcg(&g_partial[tid]);
        #pragma unroll
        for (int o = 16; o; o >>= 1) s += __shfl_xor_sync(0xffffffffu, s, o);
        if (cx == 0) redN[cy] = s;
        __syncthreads();
        if (tid < 16) {
            s = redN[tid];
            #pragma unroll
            for (int o = 8; o; o >>= 1) s += __shfl_xor_sync(0xffffu, s, o);
            if (tid == 0) {
                *out = s / (512.0f + 1e-8f);
                g_count = 0;               // reset for next graph replay
            }
        }
    }
}

extern "C" void kernel_launch(void* const* d_in, const int* in_sizes, int n_in,
                              void* d_out, int out_size)
{
    const float* pred = (const float*)d_in[0];
    const float* tgt  = (const float*)d_in[1];
    const float* vis  = (const float*)d_in[2];
    const float* grid = (const float*)d_in[3];
    gkl_fused_kernel<<<BN, 512>>>(pred, tgt, vis, grid, (float*)d_out);
}